// round 2
// baseline (speedup 1.0000x reference)
#include <cuda_runtime.h>
#include <cuda_bf16.h>

// Problem constants
#define NOBS    64     // input feature dim
#define HID     100    // hidden width
#define LAYERS  100    // number of hidden layers
#define SAMPLES 64     // samples per block
#define SP      68     // h row stride in floats (mult of 4 for 16B align; 68%32=4 limits store conflicts)
#define NTHREADS 200   // blockDim = (8 sample-groups, 25 output-groups)

// ---- packed f32x2 helpers (Blackwell sm_103a) ----
__device__ __forceinline__ unsigned long long dup2(float x) {
    unsigned long long r;
    asm("mov.b64 %0, {%1, %1};" : "=l"(r) : "f"(x));
    return r;
}
__device__ __forceinline__ unsigned long long ffma2(unsigned long long a,
                                                    unsigned long long b,
                                                    unsigned long long c) {
    unsigned long long d;
    asm("fma.rn.f32x2 %0, %1, %2, %3;" : "=l"(d) : "l"(a), "l"(b), "l"(c));
    return d;
}

extern __shared__ float smem[];  // hbuf0[HID][SP], hbuf1[HID][SP]

// One dense layer: hout[j][s] = leaky(sum_i hin[i][s] * Wl[i][j] + bl[j])
// Thread (sg, og) computes samples [8*sg, 8*sg+8) x outputs [4*og, 4*og+4).
// Samples are packed in f32x2 pairs (so h loads are direct LDS.128 -> operand pairs).
template <int K>
__device__ __forceinline__ void dense_layer(const float* __restrict__ Wl,
                                            const float* __restrict__ bl,
                                            const float* hin, float* hout,
                                            int sg, int og) {
    const int s0 = sg * 8;
    const int j0 = og * 4;

    unsigned long long acc[4][4];  // [sample-pair p][output jj]
    {
        unsigned long long b0 = dup2(bl[j0 + 0]);
        unsigned long long b1 = dup2(bl[j0 + 1]);
        unsigned long long b2 = dup2(bl[j0 + 2]);
        unsigned long long b3 = dup2(bl[j0 + 3]);
#pragma unroll
        for (int p = 0; p < 4; p++) {
            acc[p][0] = b0; acc[p][1] = b1; acc[p][2] = b2; acc[p][3] = b3;
        }
    }

#pragma unroll 4
    for (int i = 0; i < K; i++) {
        // 4 weights for this i, outputs j0..j0+3 (16B aligned: rows are 100 floats, j0 mult of 4)
        float4 w = *reinterpret_cast<const float4*>(Wl + i * HID + j0);
        unsigned long long wd0 = dup2(w.x);
        unsigned long long wd1 = dup2(w.y);
        unsigned long long wd2 = dup2(w.z);
        unsigned long long wd3 = dup2(w.w);

        // 8 samples = 4 f32x2 pairs, two LDS.128 (base 16B-aligned: SP*4=272 mult of 16, s0*4=32B mult of 16)
        const ulonglong2* hp = reinterpret_cast<const ulonglong2*>(hin + i * SP + s0);
        ulonglong2 h01 = hp[0];
        ulonglong2 h23 = hp[1];
        unsigned long long hv[4] = {h01.x, h01.y, h23.x, h23.y};

#pragma unroll
        for (int p = 0; p < 4; p++) {
            acc[p][0] = ffma2(hv[p], wd0, acc[p][0]);
            acc[p][1] = ffma2(hv[p], wd1, acc[p][1]);
            acc[p][2] = ffma2(hv[p], wd2, acc[p][2]);
            acc[p][3] = ffma2(hv[p], wd3, acc[p][3]);
        }
    }

    // LeakyReLU + store (sample-pairs are contiguous -> vectorized 8B shared stores)
#pragma unroll
    for (int jj = 0; jj < 4; jj++) {
#pragma unroll
        for (int p = 0; p < 4; p++) {
            float2 v = *reinterpret_cast<float2*>(&acc[p][jj]);
            v.x = v.x >= 0.0f ? v.x : 0.01f * v.x;
            v.y = v.y >= 0.0f ? v.y : 0.01f * v.y;
            *reinterpret_cast<float2*>(hout + (j0 + jj) * SP + s0 + 2 * p) = v;
        }
    }
}

__global__ void __launch_bounds__(NTHREADS, 3)
mlp_kernel(const float* __restrict__ x,
           const float* __restrict__ W_in, const float* __restrict__ b_in,
           const float* __restrict__ Ws,   const float* __restrict__ bs,
           const float* __restrict__ W_out, const float* __restrict__ b_out,
           float* __restrict__ out, int nsamples) {
    float* hbuf0 = smem;
    float* hbuf1 = smem + HID * SP;

    const int sg = threadIdx.x;     // 0..7   sample group
    const int og = threadIdx.y;     // 0..24  output group
    const int t  = sg + 8 * og;     // 0..199
    const int sbase = blockIdx.x * SAMPLES;

    // Load x tile (transposed) into hbuf0 rows 0..63
    for (int idx = t; idx < NOBS * SAMPLES; idx += NTHREADS) {
        int i = idx % NOBS;
        int s = idx / NOBS;
        int gs = sbase + s;
        float v = (gs < nsamples) ? x[gs * NOBS + i] : 0.0f;
        hbuf0[i * SP + s] = v;
    }
    __syncthreads();

    // Input layer: K=64
    dense_layer<NOBS>(W_in, b_in, hbuf0, hbuf1, sg, og);

    // 100 hidden layers, ping-pong
    for (int l = 0; l < LAYERS; l++) {
        __syncthreads();
        const float* hin = (l & 1) ? hbuf0 : hbuf1;
        float*       hout = (l & 1) ? hbuf1 : hbuf0;
        dense_layer<HID>(Ws + (size_t)l * HID * HID, bs + l * HID, hin, hout, sg, og);
    }
    __syncthreads();
    // After l=99 (odd): final activations in hbuf1.

    // Output head: one thread per sample (conflict-free LDS: consecutive t -> consecutive banks)
    if (t < SAMPLES) {
        int gs = sbase + t;
        if (gs < nsamples) {
            float a = b_out[0];
#pragma unroll 4
            for (int i = 0; i < HID; i++)
                a += hbuf1[i * SP + t] * W_out[i];
            a = tanhf(a);
            out[gs] = a * 4.5f + 5.5f;   // (tanh+1)/2*(10-1)+1
        }
    }
}

extern "C" void kernel_launch(void* const* d_in, const int* in_sizes, int n_in,
                              void* d_out, int out_size) {
    const float* x     = (const float*)d_in[0];
    const float* W_in  = (const float*)d_in[1];
    const float* b_in  = (const float*)d_in[2];
    const float* Ws    = (const float*)d_in[3];
    const float* bs    = (const float*)d_in[4];
    const float* W_out = (const float*)d_in[5];
    const float* b_out = (const float*)d_in[6];
    float* out = (float*)d_out;

    int nsamples = in_sizes[0] / NOBS;
    int nblocks  = (nsamples + SAMPLES - 1) / SAMPLES;

    size_t shmem = 2 * HID * SP * sizeof(float);  // 54,400 B > 48K default
    static bool attr_done = false;
    // setting the attribute is idempotent and not a stream op; safe under graph capture
    cudaFuncSetAttribute(mlp_kernel, cudaFuncAttributeMaxDynamicSharedMemorySize, (int)shmem);
    (void)attr_done;

    mlp_kernel<<<nblocks, dim3(8, 25), shmem>>>(x, W_in, b_in, Ws, bs, W_out, b_out,
                                                out, nsamples);
}

// round 4
// speedup vs baseline: 3.7783x; 3.7783x over previous
#include <cuda_runtime.h>
#include <cuda_bf16.h>
#include <cstdint>

// ============================================================
// Actor MLP via warp-level mma.sync (bf16x3 split precision).
// Each warp owns 16 samples; activations live in registers the
// whole 101-layer chain (D-frag layout == next A-frag layout).
// Weights streamed via cp.async double-buffer in frag-permuted
// layout (1 LDS.64 per B-fragment per lane, conflict-free).
// ============================================================

#define NF 13          // n-fragments (8 wide)  -> N = 104 (>=100)
#define KF 7           // k-fragments (16 wide) -> K = 112 (>=100)
#define LOOFF 23296    // lo-plane offset inside a layer chunk (7*13*32*8)
#define CHUNK 49152    // padded per-layer chunk (12 * 4096)
#define NLAYERS 101    // layer 0 = W_in, layers 1..100 = hidden

__device__ __align__(16) unsigned char g_WP[NLAYERS * CHUNK];    // ~4.97 MB
__device__ __align__(16) float2 g_BP[NLAYERS * NF * 4];
__device__ __align__(16) float2 g_WOUTP[NF * 4];

// ---- helpers ----
__device__ __forceinline__ uint32_t smem_u32(const void* p) {
    uint32_t a;
    asm("{ .reg .u64 t; cvta.to.shared.u64 t, %1; cvt.u32.u64 %0, t; }" : "=r"(a) : "l"(p));
    return a;
}
__device__ __forceinline__ float bf16lo(uint32_t p) { return __uint_as_float(p << 16); }
__device__ __forceinline__ float bf16hi(uint32_t p) { return __uint_as_float(p & 0xFFFF0000u); }
// pack {lower=lo_val, upper=hi_val} as bf16x2 (cvt: first src -> upper half)
__device__ __forceinline__ uint32_t packbf(float lo_val, float hi_val) {
    uint32_t r;
    asm("cvt.rn.bf16x2.f32 %0, %1, %2;" : "=r"(r) : "f"(hi_val), "f"(lo_val));
    return r;
}
__device__ __forceinline__ uint2 lds64(uint32_t a) {
    uint2 v;
    asm("ld.shared.v2.u32 {%0,%1}, [%2];" : "=r"(v.x), "=r"(v.y) : "r"(a));
    return v;
}
__device__ __forceinline__ void cpa16(uint32_t dst, const void* src) {
    asm volatile("cp.async.cg.shared.global [%0], [%1], 16;" :: "r"(dst), "l"(src) : "memory");
}
#define CP_COMMIT() asm volatile("cp.async.commit_group;" ::: "memory")
#define CP_WAIT1()  asm volatile("cp.async.wait_group 1;" ::: "memory")
#define CP_WAIT0()  asm volatile("cp.async.wait_group 0;" ::: "memory")

__device__ __forceinline__ void hmma(float* d, const uint32_t* a, uint2 b) {
    asm("mma.sync.aligned.m16n8k16.row.col.f32.bf16.bf16.f32 "
        "{%0,%1,%2,%3}, {%4,%5,%6,%7}, {%8,%9}, {%0,%1,%2,%3};"
        : "+f"(d[0]), "+f"(d[1]), "+f"(d[2]), "+f"(d[3])
        : "r"(a[0]), "r"(a[1]), "r"(a[2]), "r"(a[3]), "r"(b.x), "r"(b.y));
}
__device__ __forceinline__ float leaky(float v) {
    return fmaxf(v, 0.0f) + 0.01f * fminf(v, 0.0f);
}

// ============================================================
// prep: fragment-permuted, hi/lo-split weights + bias tables
//   frag element (L, kf, nf, lane): n = nf*8 + lane/4, k = kf*16 + 2*(lane%4)
//   uint2 = { pack(w(n,k), w(n,k+1)), pack(w(n,k+8), w(n,k+9)) }
// ============================================================
#define NWT (NLAYERS * KF * NF * 32)
__global__ void prep(const float* __restrict__ W_in, const float* __restrict__ b_in,
                     const float* __restrict__ Ws, const float* __restrict__ bs,
                     const float* __restrict__ W_out) {
    int t = blockIdx.x * 256 + threadIdx.x;
    if (t < NWT) {
        int L = t / (KF * NF * 32);
        int r = t % (KF * NF * 32);
        int kf = r / (NF * 32);
        int r2 = r % (NF * 32);
        int nf = r2 / 32, lane = r2 % 32;
        int n = nf * 8 + (lane >> 2);
        int k = kf * 16 + 2 * (lane & 3);
        float v[4];  // (k, k+1, k+8, k+9)
#pragma unroll
        for (int e = 0; e < 4; e++) {
            int kk = k + (e & 1) + (e >> 1) * 8;
            float w = 0.0f;
            if (L == 0) {
                if (kk < 64 && n < 100) w = W_in[kk * 100 + n];
            } else {
                if (kk < 100 && n < 100) w = Ws[((size_t)(L - 1) * 100 + kk) * 100 + n];
            }
            v[e] = w;
        }
        uint32_t hp0 = packbf(v[0], v[1]);
        uint32_t hp1 = packbf(v[2], v[3]);
        uint32_t lp0 = packbf(v[0] - bf16lo(hp0), v[1] - bf16hi(hp0));
        uint32_t lp1 = packbf(v[2] - bf16lo(hp1), v[3] - bf16hi(hp1));
        size_t off = (size_t)L * CHUNK + ((size_t)(kf * NF + nf) * 32 + lane) * 8;
        *(uint2*)(g_WP + off)         = make_uint2(hp0, hp1);
        *(uint2*)(g_WP + off + LOOFF) = make_uint2(lp0, lp1);
        return;
    }
    t -= NWT;
    if (t < NLAYERS * NF * 4) {
        int m = t / (NF * 4);
        int r = t % (NF * 4);
        int nf = r / 4, q = r % 4;
        int c = nf * 8 + 2 * q;
        float b0 = (c < 100)     ? (m == 0 ? b_in[c]     : bs[(m - 1) * 100 + c])     : 0.0f;
        float b1 = (c + 1 < 100) ? (m == 0 ? b_in[c + 1] : bs[(m - 1) * 100 + c + 1]) : 0.0f;
        g_BP[t] = make_float2(b0, b1);
        return;
    }
    t -= NLAYERS * NF * 4;
    if (t < NF * 4) {
        int nf = t / 4, q = t % 4;
        int c = nf * 8 + 2 * q;
        g_WOUTP[t] = make_float2(c < 100 ? W_out[c] : 0.0f,
                                 c + 1 < 100 ? W_out[c + 1] : 0.0f);
    }
}

// ============================================================
// main kernel: 256 threads (8 warps x 16 samples = 128/block)
// ============================================================
__global__ void __launch_bounds__(256, 2)
actor(const float* __restrict__ x, const float* __restrict__ b_out,
      float* __restrict__ out, int nsamples) {
    extern __shared__ unsigned char sm[];
    const uint32_t smb = smem_u32(sm);
    const int tid = threadIdx.x, lane = tid & 31, warp = tid >> 5;
    const int s0 = blockIdx.x * 128 + warp * 16;
    const int r = lane >> 2, kc = 2 * (lane & 3);
    const bool vlo = (s0 + r) < nsamples;
    const bool vhi = (s0 + r + 8) < nsamples;

    // ---- layer-0 A fragments straight from x (K=64 -> kf 0..3) ----
    uint32_t Ah[KF][4], Al[KF][4];
    {
        const float* xb = x + (size_t)s0 * 64;
#pragma unroll
        for (int kf = 0; kf < 4; kf++) {
            int k = kf * 16 + kc;
            float2 p00 = vlo ? *(const float2*)(xb + (size_t)r * 64 + k)       : make_float2(0.f, 0.f);
            float2 p01 = vlo ? *(const float2*)(xb + (size_t)r * 64 + k + 8)   : make_float2(0.f, 0.f);
            float2 p10 = vhi ? *(const float2*)(xb + (size_t)(r + 8) * 64 + k)     : make_float2(0.f, 0.f);
            float2 p11 = vhi ? *(const float2*)(xb + (size_t)(r + 8) * 64 + k + 8) : make_float2(0.f, 0.f);
            uint32_t h0 = packbf(p00.x, p00.y), h1 = packbf(p10.x, p10.y);
            uint32_t h2 = packbf(p01.x, p01.y), h3 = packbf(p11.x, p11.y);
            Ah[kf][0] = h0; Ah[kf][1] = h1; Ah[kf][2] = h2; Ah[kf][3] = h3;
            Al[kf][0] = packbf(p00.x - bf16lo(h0), p00.y - bf16hi(h0));
            Al[kf][1] = packbf(p10.x - bf16lo(h1), p10.y - bf16hi(h1));
            Al[kf][2] = packbf(p01.x - bf16lo(h2), p01.y - bf16hi(h2));
            Al[kf][3] = packbf(p11.x - bf16lo(h3), p11.y - bf16hi(h3));
        }
#pragma unroll
        for (int kf = 4; kf < KF; kf++) {
            Ah[kf][0] = Ah[kf][1] = Ah[kf][2] = Ah[kf][3] = 0u;
            Al[kf][0] = Al[kf][1] = Al[kf][2] = Al[kf][3] = 0u;
        }
    }

    // ---- initial copies: layer 0 -> buf0, layer 1 -> buf1 ----
    {
        const unsigned char* s0p = g_WP + tid * 16;
        const unsigned char* s1p = g_WP + CHUNK + tid * 16;
        uint32_t d0 = smb + tid * 16, d1 = smb + CHUNK + tid * 16;
#pragma unroll
        for (int i = 0; i < 12; i++) cpa16(d0 + i * 4096, s0p + (size_t)i * 4096);
        CP_COMMIT();
#pragma unroll
        for (int i = 0; i < 12; i++) cpa16(d1 + i * 4096, s1p + (size_t)i * 4096);
        CP_COMMIT();
        CP_WAIT1();
        __syncthreads();
    }

    float po0 = 0.0f, po1 = 0.0f;  // head partials (rows r, r+8)

#pragma unroll 1
    for (int m = 0; m <= 100; m++) {
        const uint32_t bufA = smb + (uint32_t)(m & 1) * CHUNK;

        float D[NF][4];
#pragma unroll
        for (int nf = 0; nf < NF; nf++) {
            D[nf][0] = 0.f; D[nf][1] = 0.f; D[nf][2] = 0.f; D[nf][3] = 0.f;
        }

        // ---- 3-product bf16 GEMM from frag-permuted smem ----
#pragma unroll
        for (int kf = 0; kf < KF; kf++) {
            uint32_t ad = bufA + (uint32_t)(kf * NF) * 256 + lane * 8;
#pragma unroll
            for (int nf = 0; nf < NF; nf++) {
                uint2 bh = lds64(ad);
                hmma(D[nf], Ah[kf], bh);
                hmma(D[nf], Al[kf], bh);
                uint2 bl = lds64(ad + LOOFF);
                hmma(D[nf], Ah[kf], bl);
                ad += 256;
            }
        }

        __syncthreads();  // everyone done reading bufA

        // prefetch layer m+2 into bufA (overlaps with epilogue)
        const bool pf = (m + 2 <= 100);
        if (pf) {
            const unsigned char* sp = g_WP + (size_t)(m + 2) * CHUNK + tid * 16;
            uint32_t dp = bufA + tid * 16;
#pragma unroll
            for (int i = 0; i < 12; i++) cpa16(dp + i * 4096, sp + (size_t)i * 4096);
            CP_COMMIT();
        }

        // ---- epilogue (registers only): bias + leaky, then split ----
        if (m < 100) {
#pragma unroll
            for (int nf = 0; nf < NF; nf++) {
                float2 bv = g_BP[(m * NF + nf) * 4 + (lane & 3)];
                D[nf][0] = leaky(D[nf][0] + bv.x);
                D[nf][1] = leaky(D[nf][1] + bv.y);
                D[nf][2] = leaky(D[nf][2] + bv.x);
                D[nf][3] = leaky(D[nf][3] + bv.y);
            }
            // rebuild A frags: A[t] regs {0,1} <- D[2t]{c0,c1},{c2,c3}; regs {2,3} <- D[2t+1]
#pragma unroll
            for (int t2 = 0; t2 < 6; t2++) {
                const float* d0 = D[2 * t2];
                const float* d1 = D[2 * t2 + 1];
                uint32_t h0 = packbf(d0[0], d0[1]), h1 = packbf(d0[2], d0[3]);
                uint32_t h2 = packbf(d1[0], d1[1]), h3 = packbf(d1[2], d1[3]);
                Ah[t2][0] = h0; Ah[t2][1] = h1; Ah[t2][2] = h2; Ah[t2][3] = h3;
                Al[t2][0] = packbf(d0[0] - bf16lo(h0), d0[1] - bf16hi(h0));
                Al[t2][1] = packbf(d0[2] - bf16lo(h1), d0[3] - bf16hi(h1));
                Al[t2][2] = packbf(d1[0] - bf16lo(h2), d1[1] - bf16hi(h2));
                Al[t2][3] = packbf(d1[2] - bf16lo(h3), d1[3] - bf16hi(h3));
            }
            {   // t2 = 6: cols 96..103 from D[12]; cols 104..111 are zero-pad
                const float* d0 = D[12];
                uint32_t h0 = packbf(d0[0], d0[1]), h1 = packbf(d0[2], d0[3]);
                Ah[6][0] = h0; Ah[6][1] = h1; Ah[6][2] = 0u; Ah[6][3] = 0u;
                Al[6][0] = packbf(d0[0] - bf16lo(h0), d0[1] - bf16hi(h0));
                Al[6][1] = packbf(d0[2] - bf16lo(h1), d0[3] - bf16hi(h1));
                Al[6][2] = 0u; Al[6][3] = 0u;
            }
        } else {
            // head: h = leaky(layer-100 out), partial dot with W_out
#pragma unroll
            for (int nf = 0; nf < NF; nf++) {
                float2 bv = g_BP[(100 * NF + nf) * 4 + (lane & 3)];
                float2 w  = g_WOUTP[nf * 4 + (lane & 3)];
                po0 += leaky(D[nf][0] + bv.x) * w.x + leaky(D[nf][1] + bv.y) * w.y;
                po1 += leaky(D[nf][2] + bv.x) * w.x + leaky(D[nf][3] + bv.y) * w.y;
            }
        }

        if (pf) CP_WAIT1(); else CP_WAIT0();
        __syncthreads();  // layer m+1 visible to all
    }

    // ---- head reduce across the 4 lanes sharing a row ----
    po0 += __shfl_xor_sync(0xffffffff, po0, 1);
    po0 += __shfl_xor_sync(0xffffffff, po0, 2);
    po1 += __shfl_xor_sync(0xffffffff, po1, 1);
    po1 += __shfl_xor_sync(0xffffffff, po1, 2);
    if ((lane & 3) == 0) {
        float bo = b_out[0];
        if (vlo) out[s0 + r]     = tanhf(po0 + bo) * 4.5f + 5.5f;
        if (vhi) out[s0 + r + 8] = tanhf(po1 + bo) * 4.5f + 5.5f;
    }
}

extern "C" void kernel_launch(void* const* d_in, const int* in_sizes, int n_in,
                              void* d_out, int out_size) {
    const float* x     = (const float*)d_in[0];
    const float* W_in  = (const float*)d_in[1];
    const float* b_in  = (const float*)d_in[2];
    const float* Ws    = (const float*)d_in[3];
    const float* bs    = (const float*)d_in[4];
    const float* W_out = (const float*)d_in[5];
    const float* b_out = (const float*)d_in[6];
    float* out = (float*)d_out;

    int nsamples = in_sizes[0] / 64;
    int nblocks  = (nsamples + 127) / 128;

    const int PREP_TOTAL = NWT + NLAYERS * NF * 4 + NF * 4;
    prep<<<(PREP_TOTAL + 255) / 256, 256>>>(W_in, b_in, Ws, bs, W_out);

    size_t shmem = 2 * CHUNK;  // 98304
    cudaFuncSetAttribute(actor, cudaFuncAttributeMaxDynamicSharedMemorySize, (int)shmem);
    actor<<<nblocks, 256, shmem>>>(x, b_out, out, nsamples);
}

// round 6
// speedup vs baseline: 3.7986x; 1.0054x over previous
#include <cuda_runtime.h>
#include <cuda_bf16.h>
#include <cstdint>

// ============================================================
// Actor MLP via warp-level mma.sync (bf16x3 split precision).
// Each warp owns 16 samples; activations live in registers the
// whole 101-layer chain (D-frag layout == next A-frag layout).
// Weights streamed via cp.async double-buffer, frag-permuted +
// hi/lo interleaved (one LDS.128 per (kf,nf) fragment).
// ============================================================

#define NF 13          // n-fragments (8 wide)  -> N = 104 (>=100)
#define KF 7           // k-fragments (16 wide) -> K = 112 (>=100)
#define CHUNK 49152    // per-layer chunk stride (12*4096; >= 7*13*32*16 = 46592)
#define NLAYERS 101    // layer 0 = W_in, layers 1..100 = hidden

__device__ __align__(16) unsigned char g_WP[NLAYERS * CHUNK];    // ~4.97 MB
__device__ __align__(16) float2 g_BP[NLAYERS * NF * 4];
__device__ __align__(16) float2 g_WOUTP[NF * 4];

// ---- helpers ----
__device__ __forceinline__ uint32_t smem_u32(const void* p) {
    uint32_t a;
    asm("{ .reg .u64 t; cvta.to.shared.u64 t, %1; cvt.u32.u64 %0, t; }" : "=r"(a) : "l"(p));
    return a;
}
__device__ __forceinline__ float bf16lo(uint32_t p) { return __uint_as_float(p << 16); }
__device__ __forceinline__ float bf16hi(uint32_t p) { return __uint_as_float(p & 0xFFFF0000u); }
// pack {lower=lo_val, upper=hi_val} as bf16x2 (cvt: first src -> upper half)
__device__ __forceinline__ uint32_t packbf(float lo_val, float hi_val) {
    uint32_t r;
    asm("cvt.rn.bf16x2.f32 %0, %1, %2;" : "=r"(r) : "f"(hi_val), "f"(lo_val));
    return r;
}
__device__ __forceinline__ uint4 lds128(uint32_t a) {
    uint4 v;
    asm("ld.shared.v4.u32 {%0,%1,%2,%3}, [%4];"
        : "=r"(v.x), "=r"(v.y), "=r"(v.z), "=r"(v.w) : "r"(a));
    return v;
}
__device__ __forceinline__ void cpa16(uint32_t dst, const void* src) {
    asm volatile("cp.async.cg.shared.global [%0], [%1], 16;" :: "r"(dst), "l"(src) : "memory");
}
#define CP_COMMIT() asm volatile("cp.async.commit_group;" ::: "memory")
#define CP_WAIT1()  asm volatile("cp.async.wait_group 1;" ::: "memory")
#define CP_WAIT0()  asm volatile("cp.async.wait_group 0;" ::: "memory")

__device__ __forceinline__ void hmma(float* d, const uint32_t* a, uint32_t b0, uint32_t b1) {
    asm("mma.sync.aligned.m16n8k16.row.col.f32.bf16.bf16.f32 "
        "{%0,%1,%2,%3}, {%4,%5,%6,%7}, {%8,%9}, {%0,%1,%2,%3};"
        : "+f"(d[0]), "+f"(d[1]), "+f"(d[2]), "+f"(d[3])
        : "r"(a[0]), "r"(a[1]), "r"(a[2]), "r"(a[3]), "r"(b0), "r"(b1));
}
__device__ __forceinline__ float leaky(float v) {
    return fmaxf(v, 0.0f) + 0.01f * fminf(v, 0.0f);
}

// ============================================================
// prep: fragment-permuted weights, hi/lo interleaved per lane:
//   uint4 @ (L*CHUNK + ((kf*NF+nf)*32 + lane)*16) =
//     { hi(k,k+1), hi(k+8,k+9), lo(k,k+1), lo(k+8,k+9) }
//   with n = nf*8 + lane/4, k = kf*16 + 2*(lane%4)
// ============================================================
#define NWT (NLAYERS * KF * NF * 32)
__global__ void prep(const float* __restrict__ W_in, const float* __restrict__ b_in,
                     const float* __restrict__ Ws, const float* __restrict__ bs,
                     const float* __restrict__ W_out) {
    int t = blockIdx.x * 256 + threadIdx.x;
    if (t < NWT) {
        int L = t / (KF * NF * 32);
        int r = t % (KF * NF * 32);
        int kf = r / (NF * 32);
        int r2 = r % (NF * 32);
        int nf = r2 / 32, lane = r2 % 32;
        int n = nf * 8 + (lane >> 2);
        int k = kf * 16 + 2 * (lane & 3);
        float v[4];  // (k, k+1, k+8, k+9)
#pragma unroll
        for (int e = 0; e < 4; e++) {
            int kk = k + (e & 1) + (e >> 1) * 8;
            float w = 0.0f;
            if (L == 0) {
                if (kk < 64 && n < 100) w = W_in[kk * 100 + n];
            } else {
                if (kk < 100 && n < 100) w = Ws[((size_t)(L - 1) * 100 + kk) * 100 + n];
            }
            v[e] = w;
        }
        uint32_t hp0 = packbf(v[0], v[1]);
        uint32_t hp1 = packbf(v[2], v[3]);
        uint32_t lp0 = packbf(v[0] - bf16lo(hp0), v[1] - bf16hi(hp0));
        uint32_t lp1 = packbf(v[2] - bf16lo(hp1), v[3] - bf16hi(hp1));
        size_t off = (size_t)L * CHUNK + ((size_t)(kf * NF + nf) * 32 + lane) * 16;
        *(uint4*)(g_WP + off) = make_uint4(hp0, hp1, lp0, lp1);
        return;
    }
    t -= NWT;
    if (t < NLAYERS * NF * 4) {
        int m = t / (NF * 4);
        int r = t % (NF * 4);
        int nf = r / 4, q = r % 4;
        int c = nf * 8 + 2 * q;
        float b0 = (c < 100)     ? (m == 0 ? b_in[c]     : bs[(m - 1) * 100 + c])     : 0.0f;
        float b1 = (c + 1 < 100) ? (m == 0 ? b_in[c + 1] : bs[(m - 1) * 100 + c + 1]) : 0.0f;
        g_BP[t] = make_float2(b0, b1);
        return;
    }
    t -= NLAYERS * NF * 4;
    if (t < NF * 4) {
        int nf = t / 4, q = t % 4;
        int c = nf * 8 + 2 * q;
        g_WOUTP[t] = make_float2(c < 100 ? W_out[c] : 0.0f,
                                 c + 1 < 100 ? W_out[c + 1] : 0.0f);
    }
}

// ============================================================
// main kernel: 256 threads (8 warps x 16 samples = 128/block)
// ============================================================
__global__ void __launch_bounds__(256, 2)
actor(const float* __restrict__ x, const float* __restrict__ b_out,
      float* __restrict__ out, int nsamples) {
    extern __shared__ unsigned char sm[];
    const uint32_t smb = smem_u32(sm);
    const int tid = threadIdx.x, lane = tid & 31, warp = tid >> 5;
    const int s0 = blockIdx.x * 128 + warp * 16;
    const int r = lane >> 2, kc = 2 * (lane & 3);
    const bool vlo = (s0 + r) < nsamples;
    const bool vhi = (s0 + r + 8) < nsamples;

    // ---- layer-0 A fragments straight from x (K=64 -> kf 0..3) ----
    uint32_t Ah[KF][4], Al[KF][4];
    {
        const float* xb = x + (size_t)s0 * 64;
#pragma unroll
        for (int kf = 0; kf < 4; kf++) {
            int k = kf * 16 + kc;
            float2 p00 = vlo ? *(const float2*)(xb + (size_t)r * 64 + k)           : make_float2(0.f, 0.f);
            float2 p01 = vlo ? *(const float2*)(xb + (size_t)r * 64 + k + 8)       : make_float2(0.f, 0.f);
            float2 p10 = vhi ? *(const float2*)(xb + (size_t)(r + 8) * 64 + k)     : make_float2(0.f, 0.f);
            float2 p11 = vhi ? *(const float2*)(xb + (size_t)(r + 8) * 64 + k + 8) : make_float2(0.f, 0.f);
            uint32_t h0 = packbf(p00.x, p00.y), h1 = packbf(p10.x, p10.y);
            uint32_t h2 = packbf(p01.x, p01.y), h3 = packbf(p11.x, p11.y);
            Ah[kf][0] = h0; Ah[kf][1] = h1; Ah[kf][2] = h2; Ah[kf][3] = h3;
            Al[kf][0] = packbf(p00.x - bf16lo(h0), p00.y - bf16hi(h0));
            Al[kf][1] = packbf(p10.x - bf16lo(h1), p10.y - bf16hi(h1));
            Al[kf][2] = packbf(p01.x - bf16lo(h2), p01.y - bf16hi(h2));
            Al[kf][3] = packbf(p11.x - bf16lo(h3), p11.y - bf16hi(h3));
        }
#pragma unroll
        for (int kf = 4; kf < KF; kf++) {
            Ah[kf][0] = Ah[kf][1] = Ah[kf][2] = Ah[kf][3] = 0u;
            Al[kf][0] = Al[kf][1] = Al[kf][2] = Al[kf][3] = 0u;
        }
    }

    // ---- initial copies: layer 0 -> buf0, layer 1 -> buf1 ----
    {
        const unsigned char* s0p = g_WP + tid * 16;
        const unsigned char* s1p = g_WP + CHUNK + tid * 16;
        uint32_t d0 = smb + tid * 16, d1 = smb + CHUNK + tid * 16;
#pragma unroll
        for (int i = 0; i < 12; i++) cpa16(d0 + i * 4096, s0p + (size_t)i * 4096);
        CP_COMMIT();
#pragma unroll
        for (int i = 0; i < 12; i++) cpa16(d1 + i * 4096, s1p + (size_t)i * 4096);
        CP_COMMIT();
        CP_WAIT1();
        __syncthreads();
    }

    float po0 = 0.0f, po1 = 0.0f;  // head partials (rows r, r+8)

#pragma unroll 1
    for (int m = 0; m <= 100; m++) {
        const uint32_t bufA = smb + (uint32_t)(m & 1) * CHUNK;

        // D initialized to bias (saves the post-GEMM bias add)
        float D[NF][4];
#pragma unroll
        for (int nf = 0; nf < NF; nf++) {
            float2 bv = g_BP[(m * NF + nf) * 4 + (lane & 3)];
            D[nf][0] = bv.x; D[nf][1] = bv.y; D[nf][2] = bv.x; D[nf][3] = bv.y;
        }

        // ---- 3-product bf16 GEMM, one LDS.128 per (kf,nf) ----
#pragma unroll
        for (int kf = 0; kf < KF; kf++) {
            uint32_t ad = bufA + (uint32_t)(kf * NF) * 512 + lane * 16;
#pragma unroll
            for (int nf = 0; nf < NF; nf++) {
                uint4 w = lds128(ad);
                hmma(D[nf], Ah[kf], w.x, w.y);   // Ahi * Whi
                hmma(D[nf], Al[kf], w.x, w.y);   // Alo * Whi
                hmma(D[nf], Ah[kf], w.z, w.w);   // Ahi * Wlo
                ad += 512;
            }
        }

        __syncthreads();  // everyone done reading bufA

        // prefetch layer m+2 into bufA (overlaps with epilogue)
        const bool pf = (m + 2 <= 100);
        if (pf) {
            const unsigned char* sp = g_WP + (size_t)(m + 2) * CHUNK + tid * 16;
            uint32_t dp = bufA + tid * 16;
#pragma unroll
            for (int i = 0; i < 12; i++) cpa16(dp + i * 4096, sp + (size_t)i * 4096);
            CP_COMMIT();
        }

        // ---- epilogue (registers only): leaky, then split ----
        if (m < 100) {
#pragma unroll
            for (int nf = 0; nf < NF; nf++) {
                D[nf][0] = leaky(D[nf][0]);
                D[nf][1] = leaky(D[nf][1]);
                D[nf][2] = leaky(D[nf][2]);
                D[nf][3] = leaky(D[nf][3]);
            }
            // rebuild A frags: A[t] regs {0,1} <- D[2t]; regs {2,3} <- D[2t+1]
#pragma unroll
            for (int t2 = 0; t2 < 6; t2++) {
                const float* d0 = D[2 * t2];
                const float* d1 = D[2 * t2 + 1];
                uint32_t h0 = packbf(d0[0], d0[1]), h1 = packbf(d0[2], d0[3]);
                uint32_t h2 = packbf(d1[0], d1[1]), h3 = packbf(d1[2], d1[3]);
                Ah[t2][0] = h0; Ah[t2][1] = h1; Ah[t2][2] = h2; Ah[t2][3] = h3;
                Al[t2][0] = packbf(d0[0] - bf16lo(h0), d0[1] - bf16hi(h0));
                Al[t2][1] = packbf(d0[2] - bf16lo(h1), d0[3] - bf16hi(h1));
                Al[t2][2] = packbf(d1[0] - bf16lo(h2), d1[1] - bf16hi(h2));
                Al[t2][3] = packbf(d1[2] - bf16lo(h3), d1[3] - bf16hi(h3));
            }
            {   // t2 = 6: cols 96..103 from D[12]; cols 104..111 are zero-pad
                const float* d0 = D[12];
                uint32_t h0 = packbf(d0[0], d0[1]), h1 = packbf(d0[2], d0[3]);
                Ah[6][0] = h0; Ah[6][1] = h1; Ah[6][2] = 0u; Ah[6][3] = 0u;
                Al[6][0] = packbf(d0[0] - bf16lo(h0), d0[1] - bf16hi(h0));
                Al[6][1] = packbf(d0[2] - bf16lo(h1), d0[3] - bf16hi(h1));
                Al[6][2] = 0u; Al[6][3] = 0u;
            }
        } else {
            // head: h = leaky(layer-100 out), partial dot with W_out
#pragma unroll
            for (int nf = 0; nf < NF; nf++) {
                float2 w = g_WOUTP[nf * 4 + (lane & 3)];
                po0 += leaky(D[nf][0]) * w.x + leaky(D[nf][1]) * w.y;
                po1 += leaky(D[nf][2]) * w.x + leaky(D[nf][3]) * w.y;
            }
        }

        if (pf) CP_WAIT1(); else CP_WAIT0();
        __syncthreads();  // layer m+1 visible to all
    }

    // ---- head reduce across the 4 lanes sharing a row ----
    po0 += __shfl_xor_sync(0xffffffff, po0, 1);
    po0 += __shfl_xor_sync(0xffffffff, po0, 2);
    po1 += __shfl_xor_sync(0xffffffff, po1, 1);
    po1 += __shfl_xor_sync(0xffffffff, po1, 2);
    if ((lane & 3) == 0) {
        float bo = b_out[0];
        if (vlo) out[s0 + r]     = tanhf(po0 + bo) * 4.5f + 5.5f;
        if (vhi) out[s0 + r + 8] = tanhf(po1 + bo) * 4.5f + 5.5f;
    }
}

extern "C" void kernel_launch(void* const* d_in, const int* in_sizes, int n_in,
                              void* d_out, int out_size) {
    const float* x     = (const float*)d_in[0];
    const float* W_in  = (const float*)d_in[1];
    const float* b_in  = (const float*)d_in[2];
    const float* Ws    = (const float*)d_in[3];
    const float* bs    = (const float*)d_in[4];
    const float* W_out = (const float*)d_in[5];
    const float* b_out = (const float*)d_in[6];
    float* out = (float*)d_out;

    int nsamples = in_sizes[0] / 64;
    int nblocks  = (nsamples + 127) / 128;

    const int PREP_TOTAL = NWT + NLAYERS * NF * 4 + NF * 4;
    prep<<<(PREP_TOTAL + 255) / 256, 256>>>(W_in, b_in, Ws, bs, W_out);

    size_t shmem = 2 * CHUNK;  // 98304
    cudaFuncSetAttribute(actor, cudaFuncAttributeMaxDynamicSharedMemorySize, (int)shmem);
    actor<<<nblocks, 256, shmem>>>(x, b_out, out, nsamples);
}